// round 13
// baseline (speedup 1.0000x reference)
#include <cuda_runtime.h>
#include <cstdint>

// Problem constants (ViT-B/16 @384: b=32, n=577, c=768, H=12, d=64, keep=0.7)
#define B   32
#define N   577
#define C   768
#define HH  12
#define DD  64
#define NK  576
#define FT  404
#define SCALE 0.125f

// Output layout: x | index | ind | class_attention | final_tokens (float32)
#define OFF_X      0ll
#define OFF_INDEX  14180352ll
#define OFF_IND    24109056ll
#define OFF_CA     24121984ll
#define OFF_FT     24140416ll

#define FULLM 0xFFFFFFFFu

// k_dots tiling: 6 c-slices of 128, 5 j-tiles of 128, 32-c stage tiles
#define CS   6
#define CSL  128
#define CT   32
#define JB   128
#define JT   640
#define JPAD 129     // conflict-free staging + reads

// ---------------- scratch ----------------------------------------------------
__device__ float g_qp[6][B * C];
__device__ float g_q[B * C];
__device__ float g_u[B * HH * C];
__device__ float g_beta[B * HH];
__device__ float g_dotsp[CS * B * HH * JT];
__device__ int   g_ind[B * FT];
__device__ int   g_cnt[B];            // monotonic arrival counters (never reset)

// ---------------- K1: qproj partials + last-block reduce. grid (32,6) -------
__global__ void __launch_bounds__(768) k_qprojp(const float* __restrict__ x,
                                                const float* __restrict__ W,
                                                const float* __restrict__ bqkv) {
    int b = blockIdx.x, s = blockIdx.y, col = threadIdx.x;
    __shared__ float xs[128];
    __shared__ int is_last;
    if (col < 128) xs[col] = x[(size_t)b * N * C + s * 128 + col];
    __syncthreads();
    float acc = 0.f;
#pragma unroll 16
    for (int i = 0; i < 128; i++)
        acc = fmaf(xs[i], W[(size_t)(s * 128 + i) * 3 * C + col], acc);
    g_qp[s][b * C + col] = acc;

    // last arriving block for this b performs the reduction
    __threadfence();
    __syncthreads();
    if (col == 0) {
        int old = atomicAdd(&g_cnt[b], 1);
        is_last = ((old % 6) == 5);
    }
    __syncthreads();
    if (is_last) {
        float r = bqkv[col];
#pragma unroll
        for (int ss = 0; ss < 6; ss++) r += __ldcg(&g_qp[ss][b * C + col]);
        g_q[b * C + col] = r;
    }
}

// ---------------- K2: u[b,h,c]; beta. grid 192 (4 cc), block 384 ------------
__global__ void k_uproj(const float* __restrict__ W,
                        const float* __restrict__ bqkv) {
    int cc0 = blockIdx.x * 4;
    int tid = threadIdx.x;
    int b = tid / HH, h = tid % HH;

    float q[DD];
    const float4* qp = (const float4*)&g_q[b * C + h * DD];
#pragma unroll
    for (int i = 0; i < DD / 4; i++) {
        float4 v = qp[i];
        q[4 * i + 0] = v.x; q[4 * i + 1] = v.y; q[4 * i + 2] = v.z; q[4 * i + 3] = v.w;
    }

    __shared__ float w[4][C];
#pragma unroll
    for (int s = 0; s < 4; s++) {
        w[s][tid]       = W[(size_t)(cc0 + s) * 3 * C + C + tid];
        w[s][tid + 384] = W[(size_t)(cc0 + s) * 3 * C + C + tid + 384];
    }
    __syncthreads();
#pragma unroll
    for (int s = 0; s < 4; s++) {
        float acc = 0.f;
#pragma unroll
        for (int d = 0; d < DD; d++) acc = fmaf(w[s][h * DD + d], q[d], acc);
        g_u[(size_t)(b * HH + h) * C + cc0 + s] = acc;
    }
    if (blockIdx.x == 0) {
        float acc = 0.f;
#pragma unroll
        for (int d = 0; d < DD; d++) acc = fmaf(bqkv[C + h * DD + d], q[d], acc);
        g_beta[tid] = acc;
    }
}

// ---------------- K3: dots partials. grid (32, CS, 5), block 128 ------------
// Phase 0: stream whole panel x->out (fulfills x copy, warms L2).
// Phase 1: CT=32 double-buffered tiles; loads now hit L2.
__global__ void __launch_bounds__(128) k_dots(const float* __restrict__ x,
                                              float* __restrict__ out) {
    int b = blockIdx.x, cs = blockIdx.y, jt = blockIdx.z, t = threadIdx.x;
    int c0 = cs * CSL;
    int jbase = jt * JB;

    __shared__ float xsT[2][CT][JPAD];
    __shared__ float usT[CSL][12];

    // stage u^T once (visible after the first in-loop barrier)
    for (int i = t; i < CSL * HH; i += 128) {
        int h = i / CSL, cc = i % CSL;
        usT[cc][h] = g_u[((size_t)b * HH + h) * C + c0 + cc];
    }

    // Phase 0: panel copy (128j x 128c = 4096 float4, 32 per thread)
#pragma unroll 8
    for (int k = 0; k < 32; k++) {
        int f = t + 128 * k;
        int jr = f >> 5, cf = f & 31;            // 32 float4 per j-row
        int j = jbase + jr;
        if (j < N) {
            size_t g = ((size_t)b * N + j) * C + c0 + cf * 4;
            *(float4*)&out[OFF_X + g] = *(const float4*)&x[g];
        }
    }

    // per-thread staging coords: 8 float4 per 32c x 128j tile
    int jr[8], fc[8], jj[8];
#pragma unroll
    for (int k = 0; k < 8; k++) {
        int f = t + 128 * k;
        jr[k] = f >> 3; fc[k] = f & 7; jj[k] = jbase + jr[k];
    }

    float4 pv[8];
    const float4 z4 = make_float4(0.f, 0.f, 0.f, 0.f);

#define LOAD_TILE(ct_) do {                                                     \
        _Pragma("unroll")                                                       \
        for (int k = 0; k < 8; k++)                                             \
            pv[k] = (jj[k] < N)                                                 \
                ? *(const float4*)&x[((size_t)b*N+jj[k])*C + c0 + (ct_) + fc[k]*4] \
                : z4;                                                           \
    } while (0)

    float acc[12];
#pragma unroll
    for (int h = 0; h < 12; h++) acc[h] = 0.f;

    LOAD_TILE(0);

#pragma unroll
    for (int tile = 0; tile < CSL / CT; tile++) {
        int buf = tile & 1;
        int ct = tile * CT;
#pragma unroll
        for (int k = 0; k < 8; k++) {
            int cc = fc[k] * 4;
            xsT[buf][cc + 0][jr[k]] = pv[k].x;
            xsT[buf][cc + 1][jr[k]] = pv[k].y;
            xsT[buf][cc + 2][jr[k]] = pv[k].z;
            xsT[buf][cc + 3][jr[k]] = pv[k].w;
        }
        if (tile + 1 < CSL / CT) LOAD_TILE(ct + CT);
        __syncthreads();
#pragma unroll
        for (int cc = 0; cc < CT; cc++) {
            const float4 u0 = *(const float4*)&usT[ct + cc][0];
            const float4 u1 = *(const float4*)&usT[ct + cc][4];
            const float4 u2 = *(const float4*)&usT[ct + cc][8];
            float xv = xsT[buf][cc][t];
            acc[0]  = fmaf(xv, u0.x, acc[0]);
            acc[1]  = fmaf(xv, u0.y, acc[1]);
            acc[2]  = fmaf(xv, u0.z, acc[2]);
            acc[3]  = fmaf(xv, u0.w, acc[3]);
            acc[4]  = fmaf(xv, u1.x, acc[4]);
            acc[5]  = fmaf(xv, u1.y, acc[5]);
            acc[6]  = fmaf(xv, u1.z, acc[6]);
            acc[7]  = fmaf(xv, u1.w, acc[7]);
            acc[8]  = fmaf(xv, u2.x, acc[8]);
            acc[9]  = fmaf(xv, u2.y, acc[9]);
            acc[10] = fmaf(xv, u2.z, acc[10]);
            acc[11] = fmaf(xv, u2.w, acc[11]);
        }
    }
#undef LOAD_TILE

    int jme = jbase + t;
    if (jme < N) {
#pragma unroll
        for (int h = 0; h < 12; h++)
            g_dotsp[((size_t)(cs * B + b) * HH + h) * JT + jme] = acc[h];
    }
}

// ---------------- K4: softmax + head-mean + top-k + ind ---------------------
// grid 32, block 768 (= 12 heads x 64 threads). Uniform barriers only.
__global__ void __launch_bounds__(768) k_finish(float* __restrict__ out,
                                                const float* __restrict__ keep_rate) {
    int b = blockIdx.x, tid = threadIdx.x;
    int h = tid >> 6, s = tid & 63;
    int lane = tid & 31, warp = tid >> 5;

    __shared__ float redm[24];
    __shared__ float reds[24];
    __shared__ float pr[12][580];
    __shared__ float4 vals4[NK / 4];
    __shared__ int wcnt[24];
    float* vals = (float*)vals4;

    float beta = g_beta[b * HH + h];

    float d[10];
    float m = -1e30f;
#pragma unroll
    for (int k = 0; k < 10; k++) {
        int j = s + 64 * k;
        float v = -1e30f;
        if (j < N) {
            float sum = beta;
#pragma unroll
            for (int cs = 0; cs < CS; cs++)
                sum += g_dotsp[((size_t)(cs * B + b) * HH + h) * JT + j];
            v = SCALE * sum;
        }
        d[k] = v;
        m = fmaxf(m, v);
    }
    for (int o = 16; o; o >>= 1) m = fmaxf(m, __shfl_xor_sync(FULLM, m, o));
    if (lane == 0) redm[warp] = m;
    __syncthreads();
    m = fmaxf(redm[2 * h], redm[2 * h + 1]);

    float e[10];
    float sm = 0.f;
#pragma unroll
    for (int k = 0; k < 10; k++) {
        e[k] = (d[k] > -1e29f) ? __expf(d[k] - m) : 0.f;
        sm += e[k];
    }
    for (int o = 16; o; o >>= 1) sm += __shfl_xor_sync(FULLM, sm, o);
    if (lane == 0) reds[warp] = sm;
    __syncthreads();
    float inv = 1.f / (reds[2 * h] + reds[2 * h + 1]);

#pragma unroll
    for (int k = 0; k < 10; k++) {
        int j = s + 64 * k;
        if (j < N) pr[h][j] = e[k] * inv;
    }
    __syncthreads();

    if (tid < NK) {
        float c = 0.f;
#pragma unroll
        for (int hh = 0; hh < 12; hh++) c += pr[hh][tid + 1];
        c *= (1.f / 12.f);
        vals[tid] = c;
        out[OFF_CA + (size_t)b * NK + tid] = c;
    }
    __syncthreads();

    int K = (int)ceilf(keep_rate[0] * (float)NK);   // 404

    int i = (tid < NK) ? tid : 0;
    float vi = vals[i];
    int rank = 0;
#pragma unroll 4
    for (int jq = 0; jq < NK / 4; jq++) {
        float4 v = vals4[jq];
        int j = jq * 4;
        rank += (v.x > vi) || (v.x == vi && (j + 0) < i);
        rank += (v.y > vi) || (v.y == vi && (j + 1) < i);
        rank += (v.z > vi) || (v.z == vi && (j + 2) < i);
        rank += (v.w > vi) || (v.w == vi && (j + 3) < i);
    }
    bool sel = (tid < NK) && (rank < K);
    unsigned mm = __ballot_sync(FULLM, sel);
    if (lane == 0) wcnt[warp] = __popc(mm);
    __syncthreads();
    int base = 0;
    for (int w = 0; w < warp; w++) base += wcnt[w];
    int pos = base + __popc(mm & ((1u << lane) - 1u));
    if (sel) {
        out[OFF_IND + (size_t)b * FT + pos] = (float)i;
        g_ind[b * FT + pos] = i;
    }
    if (b == 0 && tid == 0) out[OFF_FT] = (float)K;
}

// ---------------- K5: index broadcast, full-chip ----------------------------
__global__ void k_index(float* __restrict__ out) {
    int t = threadIdx.x;
    int r0 = blockIdx.x * 4;
    float4* op = (float4*)(out + OFF_INDEX) + (size_t)r0 * (C / 4);
#pragma unroll
    for (int k = 0; k < 3; k++) {
        int idx = t + 256 * k;
        int r = idx / (C / 4);
        int col = idx - r * (C / 4);
        float v = (float)g_ind[r0 + r];
        op[(size_t)r * (C / 4) + col] = make_float4(v, v, v, v);
    }
}

// ---------------- launch -----------------------------------------------------
extern "C" void kernel_launch(void* const* d_in, const int* in_sizes, int n_in,
                              void* d_out, int out_size) {
    const float* x    = (const float*)d_in[0];
    const float* kr   = (const float*)d_in[1];
    const float* Wqkv = (const float*)d_in[2];
    const float* bqkv = (const float*)d_in[3];
    float* out = (float*)d_out;

    k_qprojp<<<dim3(B, 6), C>>>(x, Wqkv, bqkv);   // includes q reduce
    k_uproj<<<192, 384>>>(Wqkv, bqkv);
    k_dots<<<dim3(B, CS, 5), 128>>>(x, out);      // includes x -> out copy
    k_finish<<<B, 768>>>(out, kr);
    k_index<<<(B * FT) / 4, 256>>>(out);
}

// round 14
// speedup vs baseline: 1.2435x; 1.2435x over previous
#include <cuda_runtime.h>
#include <cstdint>

// Problem constants (ViT-B/16 @384: b=32, n=577, c=768, H=12, d=64, keep=0.7)
#define B   32
#define N   577
#define C   768
#define HH  12
#define DD  64
#define NK  576
#define FT  404
#define SCALE 0.125f

// Output layout: x | index | ind | class_attention | final_tokens (float32)
#define OFF_X      0ll
#define OFF_INDEX  14180352ll
#define OFF_IND    24109056ll
#define OFF_CA     24121984ll
#define OFF_FT     24140416ll

#define FULLM 0xFFFFFFFFu

// k_dots tiling: 6 c-slices of 128, 5 j-tiles of 128, 32-c stage tiles
#define CS   6
#define CSL  128
#define CT   32
#define JB   128
#define JT   640
#define JPAD 129

// ---------------- scratch ----------------------------------------------------
__device__ float g_qp[6][B * C];
__device__ float g_q[B * C];
__device__ float g_u[B * HH * C];
__device__ float g_beta[B * HH];
__device__ float g_dotsp[CS * B * HH * JT];
__device__ int   g_ind[B * FT];

// ---------------- K1a: qproj partials. grid (32,6), block 768 ---------------
__global__ void __launch_bounds__(768) k_qprojp(const float* __restrict__ x,
                                                const float* __restrict__ W) {
    int b = blockIdx.x, s = blockIdx.y, col = threadIdx.x;
    __shared__ float xs[128];
    if (col < 128) xs[col] = x[(size_t)b * N * C + s * 128 + col];
    __syncthreads();
    float acc = 0.f;
#pragma unroll 16
    for (int i = 0; i < 128; i++)
        acc = fmaf(xs[i], W[(size_t)(s * 128 + i) * 3 * C + col], acc);
    g_qp[s][b * C + col] = acc;
}

// ---------------- K1b: q = sum partials + bias. grid 32, block 768 ----------
__global__ void k_qreduce(const float* __restrict__ bq) {
    int b = blockIdx.x, col = threadIdx.x;
    float acc = bq[col];
#pragma unroll
    for (int s = 0; s < 6; s++) acc += g_qp[s][b * C + col];
    g_q[b * C + col] = acc;
}

// ---------------- K2: u[b,h,c]; beta. grid 192 (4 cc), block 384 ------------
__global__ void k_uproj(const float* __restrict__ W,
                        const float* __restrict__ bqkv) {
    int cc0 = blockIdx.x * 4;
    int tid = threadIdx.x;
    int b = tid / HH, h = tid % HH;

    float q[DD];
    const float4* qp = (const float4*)&g_q[b * C + h * DD];
#pragma unroll
    for (int i = 0; i < DD / 4; i++) {
        float4 v = qp[i];
        q[4 * i + 0] = v.x; q[4 * i + 1] = v.y; q[4 * i + 2] = v.z; q[4 * i + 3] = v.w;
    }

    __shared__ float w[4][C];
#pragma unroll
    for (int s = 0; s < 4; s++) {
        w[s][tid]       = W[(size_t)(cc0 + s) * 3 * C + C + tid];
        w[s][tid + 384] = W[(size_t)(cc0 + s) * 3 * C + C + tid + 384];
    }
    __syncthreads();
#pragma unroll
    for (int s = 0; s < 4; s++) {
        float acc = 0.f;
#pragma unroll
        for (int d = 0; d < DD; d++) acc = fmaf(w[s][h * DD + d], q[d], acc);
        g_u[(size_t)(b * HH + h) * C + cc0 + s] = acc;
    }
    if (blockIdx.x == 0) {
        float acc = 0.f;
#pragma unroll
        for (int d = 0; d < DD; d++) acc = fmaf(bqkv[C + h * DD + d], q[d], acc);
        g_beta[tid] = acc;
    }
}

// ---------------- K3: dots partials. grid (32, CS, 5), block 128 ------------
// CT=32 double-buffered tiles; fused x->out copy; register prefetch depth 1.
// (exact config that measured 32.3us / total 112.7us)
__global__ void __launch_bounds__(128) k_dots(const float* __restrict__ x,
                                              float* __restrict__ out) {
    int b = blockIdx.x, cs = blockIdx.y, jt = blockIdx.z, t = threadIdx.x;
    int c0 = cs * CSL;
    int jbase = jt * JB;

    __shared__ float xsT[2][CT][JPAD];
    __shared__ float usT[CSL][12];

    for (int i = t; i < CSL * HH; i += 128) {
        int h = i / CSL, cc = i % CSL;
        usT[cc][h] = g_u[((size_t)b * HH + h) * C + c0 + cc];
    }

    int jr[8], fc[8], jj[8];
#pragma unroll
    for (int k = 0; k < 8; k++) {
        int f = t + 128 * k;
        jr[k] = f >> 3; fc[k] = f & 7; jj[k] = jbase + jr[k];
    }

    float4 pv[8];
    const float4 z4 = make_float4(0.f, 0.f, 0.f, 0.f);

#define LOAD_TILE(ct_) do {                                                     \
        _Pragma("unroll")                                                       \
        for (int k = 0; k < 8; k++)                                             \
            pv[k] = (jj[k] < N)                                                 \
                ? *(const float4*)&x[((size_t)b*N+jj[k])*C + c0 + (ct_) + fc[k]*4] \
                : z4;                                                           \
    } while (0)

    float acc[12];
#pragma unroll
    for (int h = 0; h < 12; h++) acc[h] = 0.f;

    LOAD_TILE(0);

#pragma unroll
    for (int tile = 0; tile < CSL / CT; tile++) {
        int buf = tile & 1;
        int ct = tile * CT;
#pragma unroll
        for (int k = 0; k < 8; k++) {
            if (jj[k] < N)
                *(float4*)&out[OFF_X + ((size_t)b*N+jj[k])*C + c0 + ct + fc[k]*4] = pv[k];
            int cc = fc[k] * 4;
            xsT[buf][cc + 0][jr[k]] = pv[k].x;
            xsT[buf][cc + 1][jr[k]] = pv[k].y;
            xsT[buf][cc + 2][jr[k]] = pv[k].z;
            xsT[buf][cc + 3][jr[k]] = pv[k].w;
        }
        if (tile + 1 < CSL / CT) LOAD_TILE(ct + CT);
        __syncthreads();
#pragma unroll
        for (int cc = 0; cc < CT; cc++) {
            const float4 u0 = *(const float4*)&usT[ct + cc][0];
            const float4 u1 = *(const float4*)&usT[ct + cc][4];
            const float4 u2 = *(const float4*)&usT[ct + cc][8];
            float xv = xsT[buf][cc][t];
            acc[0]  = fmaf(xv, u0.x, acc[0]);
            acc[1]  = fmaf(xv, u0.y, acc[1]);
            acc[2]  = fmaf(xv, u0.z, acc[2]);
            acc[3]  = fmaf(xv, u0.w, acc[3]);
            acc[4]  = fmaf(xv, u1.x, acc[4]);
            acc[5]  = fmaf(xv, u1.y, acc[5]);
            acc[6]  = fmaf(xv, u1.z, acc[6]);
            acc[7]  = fmaf(xv, u1.w, acc[7]);
            acc[8]  = fmaf(xv, u2.x, acc[8]);
            acc[9]  = fmaf(xv, u2.y, acc[9]);
            acc[10] = fmaf(xv, u2.z, acc[10]);
            acc[11] = fmaf(xv, u2.w, acc[11]);
        }
    }
#undef LOAD_TILE

    int jme = jbase + t;
    if (jme < N) {
#pragma unroll
        for (int h = 0; h < 12; h++)
            g_dotsp[((size_t)(cs * B + b) * HH + h) * JT + jme] = acc[h];
    }
}

// ---------------- K4: softmax + head-mean + radix-select top-k + ind --------
// grid 32, block 768 (= 12 heads x 64 threads). Uniform barriers only.
__global__ void __launch_bounds__(768) k_finish(float* __restrict__ out,
                                                const float* __restrict__ keep_rate) {
    int b = blockIdx.x, tid = threadIdx.x;
    int h = tid >> 6, s = tid & 63;
    int lane = tid & 31, warp = tid >> 5;

    __shared__ float redm[24];
    __shared__ float reds[24];
    __shared__ float pr[12][580];
    __shared__ unsigned ovals[NK];     // orderable keys
    __shared__ int bins[256];
    __shared__ int wcnt[24];
    __shared__ unsigned sh_pref;
    __shared__ int sh_krem;

    float beta = g_beta[b * HH + h];

    // ---- softmax logits ----
    float d[10];
    float m = -1e30f;
#pragma unroll
    for (int k = 0; k < 10; k++) {
        int j = s + 64 * k;
        float v = -1e30f;
        if (j < N) {
            float sum = beta;
#pragma unroll
            for (int cs = 0; cs < CS; cs++)
                sum += g_dotsp[((size_t)(cs * B + b) * HH + h) * JT + j];
            v = SCALE * sum;
        }
        d[k] = v;
        m = fmaxf(m, v);
    }
    for (int o = 16; o; o >>= 1) m = fmaxf(m, __shfl_xor_sync(FULLM, m, o));
    if (lane == 0) redm[warp] = m;
    __syncthreads();
    m = fmaxf(redm[2 * h], redm[2 * h + 1]);

    float e[10];
    float sm = 0.f;
#pragma unroll
    for (int k = 0; k < 10; k++) {
        e[k] = (d[k] > -1e29f) ? __expf(d[k] - m) : 0.f;
        sm += e[k];
    }
    for (int o = 16; o; o >>= 1) sm += __shfl_xor_sync(FULLM, sm, o);
    if (lane == 0) reds[warp] = sm;
    __syncthreads();
    float inv = 1.f / (reds[2 * h] + reds[2 * h + 1]);

#pragma unroll
    for (int k = 0; k < 10; k++) {
        int j = s + 64 * k;
        if (j < N) pr[h][j] = e[k] * inv;
    }
    __syncthreads();

    // ---- head-mean -> class_attention + orderable keys ----
    float vi = 0.f;
    if (tid < NK) {
        float c = 0.f;
#pragma unroll
        for (int hh = 0; hh < 12; hh++) c += pr[hh][tid + 1];
        c *= (1.f / 12.f);
        vi = c;
        out[OFF_CA + (size_t)b * NK + tid] = c;
        unsigned u = __float_as_uint(c);
        ovals[tid] = (u & 0x80000000u) ? ~u : (u | 0x80000000u);
    }
    __syncthreads();

    int K = (int)ceilf(keep_rate[0] * (float)NK);   // 404
    if (tid == 0) sh_krem = K;
    __syncthreads();   // sh_krem visible

    // ---- MSD radix select: find K-th largest key (exact) ----
    unsigned omine = (tid < NK) ? ovals[tid] : 0u;
#pragma unroll
    for (int pass = 3; pass >= 0; pass--) {
        int shift = pass * 8;
        if (tid < 256) bins[tid] = 0;
        __syncthreads();
        bool cand = (tid < NK) &&
                    (pass == 3 || (omine >> (shift + 8)) == sh_pref);
        if (cand) atomicAdd(&bins[(omine >> shift) & 0xFF], 1);
        __syncthreads();
        if (warp == 0) {
            int cnt[8], sc = 0;
#pragma unroll
            for (int k = 0; k < 8; k++) {
                cnt[k] = bins[255 - (lane * 8 + k)];
                sc += cnt[k];
            }
            int ex = sc;
#pragma unroll
            for (int o2 = 1; o2 < 32; o2 <<= 1) {
                int vsh = __shfl_up_sync(FULLM, ex, o2);
                if (lane >= o2) ex += vsh;
            }
            ex -= sc;                      // items strictly above this lane's chunk
            int krem = sh_krem;
            if (ex < krem && ex + sc >= krem) {   // unique winner lane
                int run = ex;
#pragma unroll
                for (int k = 0; k < 8; k++) {
                    int dd = 255 - (lane * 8 + k);
                    if (run + cnt[k] >= krem) {
                        sh_krem = krem - run;
                        sh_pref = (pass == 3) ? (unsigned)dd
                                              : ((sh_pref << 8) | (unsigned)dd);
                        break;
                    }
                    run += cnt[k];
                }
            }
        }
        __syncthreads();
    }

    unsigned othr = sh_pref;      // exact K-th largest key
    int trem = sh_krem;           // #threshold-equal items to select (by asc index)

    // ---- selection (ties resolved by ascending index, matching top_k) ----
    bool sel = false;
    if (tid < NK) {
        if (omine > othr) sel = true;
        else if (omine == othr) {
            int tp = 0;
            for (int j = 0; j < tid; j++) tp += (ovals[j] == othr);
            sel = (tp < trem);
        }
    }
    unsigned mm = __ballot_sync(FULLM, sel);
    if (lane == 0) wcnt[warp] = __popc(mm);
    __syncthreads();
    int base = 0;
    for (int w = 0; w < warp; w++) base += wcnt[w];
    int pos = base + __popc(mm & ((1u << lane) - 1u));
    if (sel) {
        out[OFF_IND + (size_t)b * FT + pos] = (float)tid;
        g_ind[b * FT + pos] = tid;
    }
    if (b == 0 && tid == 0) out[OFF_FT] = (float)K;
}

// ---------------- K5: index broadcast, full-chip ----------------------------
__global__ void k_index(float* __restrict__ out) {
    int t = threadIdx.x;
    int r0 = blockIdx.x * 4;
    float4* op = (float4*)(out + OFF_INDEX) + (size_t)r0 * (C / 4);
#pragma unroll
    for (int k = 0; k < 3; k++) {
        int idx = t + 256 * k;
        int r = idx / (C / 4);
        int col = idx - r * (C / 4);
        float v = (float)g_ind[r0 + r];
        op[(size_t)r * (C / 4) + col] = make_float4(v, v, v, v);
    }
}

// ---------------- launch -----------------------------------------------------
extern "C" void kernel_launch(void* const* d_in, const int* in_sizes, int n_in,
                              void* d_out, int out_size) {
    const float* x    = (const float*)d_in[0];
    const float* kr   = (const float*)d_in[1];
    const float* Wqkv = (const float*)d_in[2];
    const float* bqkv = (const float*)d_in[3];
    float* out = (float*)d_out;

    k_qprojp<<<dim3(B, 6), C>>>(x, Wqkv);
    k_qreduce<<<B, C>>>(bqkv);
    k_uproj<<<192, 384>>>(Wqkv, bqkv);
    k_dots<<<dim3(B, CS, 5), 128>>>(x, out);   // also copies x -> out
    k_finish<<<B, 768>>>(out, kr);
    k_index<<<(B * FT) / 4, 256>>>(out);
}